// round 2
// baseline (speedup 1.0000x reference)
#include <cuda_runtime.h>
#include <cuda_bf16.h>
#include <math.h>

#define BB 2
#define NN 1024
#define CIN 512
#define HH 16
#define DH 32
#define CZ 128

// ---------------- scratch (device globals; no allocation) ----------------
__device__ float g_mln[BB * NN * CIN];
__device__ float g_q[BB * NN * CIN];
__device__ float g_k[BB * NN * CIN];
__device__ float g_v[BB * NN * CIN];
__device__ float g_g[BB * NN * CIN];
__device__ float g_og[BB * NN * CIN];
__device__ float g_scores[(size_t)BB * HH * NN * NN];   // 128 MB

__device__ __forceinline__ float comp4(const float4 v, int u) {
    return u == 0 ? v.x : (u == 1 ? v.y : (u == 2 ? v.z : v.w));
}

// ---------------- kernel 1a: LayerNorm(m) ----------------
__global__ __launch_bounds__(128) void ln_m_kernel(const float* __restrict__ m,
                                                   const float* __restrict__ w,
                                                   const float* __restrict__ b) {
    int row = blockIdx.x;                 // b*1024 + n
    int tid = threadIdx.x;                // 128 threads, each 1 float4 (4 c)
    const float4* mp = (const float4*)m + (size_t)row * 128;
    float4 x = mp[tid];
    float s = x.x + x.y + x.z + x.w;
    float q2 = x.x * x.x + x.y * x.y + x.z * x.z + x.w * x.w;
#pragma unroll
    for (int o = 16; o; o >>= 1) {
        s  += __shfl_xor_sync(0xffffffffu, s, o);
        q2 += __shfl_xor_sync(0xffffffffu, q2, o);
    }
    __shared__ float sS[4], sQ[4];
    __shared__ float s_mu, s_rstd;
    int wid = tid >> 5, lane = tid & 31;
    if (lane == 0) { sS[wid] = s; sQ[wid] = q2; }
    __syncthreads();
    if (tid == 0) {
        float ts = sS[0] + sS[1] + sS[2] + sS[3];
        float tq = sQ[0] + sQ[1] + sQ[2] + sQ[3];
        float mu = ts * (1.0f / 512.0f);
        float var = tq * (1.0f / 512.0f) - mu * mu;
        s_mu = mu;
        s_rstd = rsqrtf(var + 1e-5f);
    }
    __syncthreads();
    float mu = s_mu, rstd = s_rstd;
    float4 w4 = ((const float4*)w)[tid];
    float4 b4 = ((const float4*)b)[tid];
    float4 o;
    o.x = (x.x - mu) * rstd * w4.x + b4.x;
    o.y = (x.y - mu) * rstd * w4.y + b4.y;
    o.z = (x.z - mu) * rstd * w4.z + b4.z;
    o.w = (x.w - mu) * rstd * w4.w + b4.w;
    ((float4*)g_mln)[(size_t)row * 128 + tid] = o;
}

// ---------------- kernel 1b: projections q,k,v,g = mln @ [wq|wk|wv|wg] ----------------
__global__ __launch_bounds__(256) void proj_kernel(const float* __restrict__ wq,
                                                   const float* __restrict__ wk,
                                                   const float* __restrict__ wv,
                                                   const float* __restrict__ wg,
                                                   const float* __restrict__ bg) {
    __shared__ float As[16][68];
    __shared__ float Bs[16][68];
    int bx = blockIdx.x;            // 0..31 : concatenated 64-col tiles (q,k,v,g)
    int by = blockIdx.y;            // 0..31 : 64-row tiles
    int tid = threadIdx.x;
    int tx = tid & 15, ty = tid >> 4;
    int sel = bx >> 3;
    int cl0 = (bx & 7) * 64;
    const float* W = (sel == 0) ? wq : (sel == 1) ? wk : (sel == 2) ? wv : wg;
    float acc[4][4] = {};
    int aRow = tid >> 2, aK4 = (tid & 3) * 4;
    int bK = tid >> 4, bC4 = (tid & 15) * 4;
    for (int k0 = 0; k0 < 512; k0 += 16) {
        float4 va = *(const float4*)(g_mln + (size_t)(by * 64 + aRow) * 512 + k0 + aK4);
        float4 vb = *(const float4*)(W + (size_t)(k0 + bK) * 512 + cl0 + bC4);
        __syncthreads();
        As[aK4 + 0][aRow] = va.x;
        As[aK4 + 1][aRow] = va.y;
        As[aK4 + 2][aRow] = va.z;
        As[aK4 + 3][aRow] = va.w;
        *(float4*)&Bs[bK][bC4] = vb;
        __syncthreads();
#pragma unroll
        for (int kk = 0; kk < 16; ++kk) {
            float4 a = *(const float4*)&As[kk][ty * 4];
            float4 b = *(const float4*)&Bs[kk][tx * 4];
            float ar[4] = {a.x, a.y, a.z, a.w};
            float br[4] = {b.x, b.y, b.z, b.w};
#pragma unroll
            for (int i = 0; i < 4; ++i)
#pragma unroll
                for (int j = 0; j < 4; ++j) acc[i][j] += ar[i] * br[j];
        }
    }
    const float qscale = 0.17677669529663687f;   // 32^-0.5
#pragma unroll
    for (int i = 0; i < 4; ++i) {
        int row = by * 64 + ty * 4 + i;
#pragma unroll
        for (int j = 0; j < 4; ++j) {
            int col = cl0 + tx * 4 + j;
            size_t oidx = (size_t)row * 512 + col;
            float v = acc[i][j];
            if (sel == 0)      g_q[oidx] = v * qscale;
            else if (sel == 1) g_k[oidx] = v;
            else if (sel == 2) g_v[oidx] = v;
            else               g_g[oidx] = 1.0f / (1.0f + __expf(-(v + bg[col])));
        }
    }
}

// ---------------- kernel 2: scores = pair_bias + mask_bias ----------------
// bias_h = rstd*(dot_h - mu*S1_h) + C0_h  with one pass over z.
__global__ __launch_bounds__(256) void bias_kernel(const float* __restrict__ z,
                                                   const float* __restrict__ mask,
                                                   const float* __restrict__ lzw,
                                                   const float* __restrict__ lzb,
                                                   const float* __restrict__ wz) {
    __shared__ float wzw[2048];
    __shared__ float s1[16], c0[16];
    int tid = threadIdx.x;
    int bq = blockIdx.x;
    int b = bq >> 10, q = bq & 1023;

    for (int idx = tid; idx < 2048; idx += 256) {
        int c = idx >> 4;
        wzw[idx] = lzw[c] * wz[idx];
    }
    __syncthreads();
    if (tid < 16) {
        float a = 0.f, bb2 = 0.f;
        for (int c = 0; c < 128; ++c) {
            a   += wzw[c * 16 + tid];
            bb2 += lzb[c] * wz[c * 16 + tid];
        }
        s1[tid] = a;
        c0[tid] = bb2;
    }
    __syncthreads();

    const float4* zb = (const float4*)z + ((size_t)bq * 1024) * 32;
    const float4* zp0 = zb + (size_t)(tid) * 32;
    const float4* zp1 = zb + (size_t)(tid + 256) * 32;
    const float4* zp2 = zb + (size_t)(tid + 512) * 32;
    const float4* zp3 = zb + (size_t)(tid + 768) * 32;

    float sm[4] = {0, 0, 0, 0}, sq[4] = {0, 0, 0, 0};
    float dot[4][16] = {};

#pragma unroll 2
    for (int c4 = 0; c4 < 32; ++c4) {
        float4 zv0 = zp0[c4];
        float4 zv1 = zp1[c4];
        float4 zv2 = zp2[c4];
        float4 zv3 = zp3[c4];
#pragma unroll
        for (int u = 0; u < 4; ++u) {
            int c = c4 * 4 + u;
            float4 w0 = *(const float4*)&wzw[c * 16 + 0];
            float4 w1 = *(const float4*)&wzw[c * 16 + 4];
            float4 w2 = *(const float4*)&wzw[c * 16 + 8];
            float4 w3 = *(const float4*)&wzw[c * 16 + 12];
            float xs[4] = {comp4(zv0, u), comp4(zv1, u), comp4(zv2, u), comp4(zv3, u)};
#pragma unroll
            for (int j = 0; j < 4; ++j) {
                float x = xs[j];
                sm[j] += x;
                sq[j] += x * x;
                dot[j][0]  += x * w0.x;  dot[j][1]  += x * w0.y;
                dot[j][2]  += x * w0.z;  dot[j][3]  += x * w0.w;
                dot[j][4]  += x * w1.x;  dot[j][5]  += x * w1.y;
                dot[j][6]  += x * w1.z;  dot[j][7]  += x * w1.w;
                dot[j][8]  += x * w2.x;  dot[j][9]  += x * w2.y;
                dot[j][10] += x * w2.z;  dot[j][11] += x * w2.w;
                dot[j][12] += x * w3.x;  dot[j][13] += x * w3.y;
                dot[j][14] += x * w3.z;  dot[j][15] += x * w3.w;
            }
        }
    }

#pragma unroll
    for (int j = 0; j < 4; ++j) {
        int k = tid + 256 * j;
        float mu = sm[j] * (1.0f / 128.0f);
        float var = sq[j] * (1.0f / 128.0f) - mu * mu;
        float rstd = rsqrtf(var + 1e-5f);
        float mb = 1e9f * (mask[b * 1024 + k] - 1.0f);
#pragma unroll
        for (int h = 0; h < 16; ++h) {
            float val = rstd * (dot[j][h] - mu * s1[h]) + c0[h] + mb;
            g_scores[(((size_t)(b * 16 + h)) * 1024 + q) * 1024 + k] = val;
        }
    }
}

// ---------------- kernel 3: scores += QK^T, softmax, AV, gate ----------------
__global__ __launch_bounds__(256) void attn_kernel() {
    __shared__ float S[8 * 1024];    // 32 KB: 8 q-rows of logits
    __shared__ float KV[64 * 33];    // K/V tile, pad 33 -> conflict free
    __shared__ float QS[8 * 32];
    int tid = threadIdx.x;
    int qt = blockIdx.x;            // 0..127
    int bh = blockIdx.y;            // 0..31
    int b = bh >> 4, h = bh & 15;
    int q0 = qt * 8;
    size_t sbase = ((size_t)bh * 1024 + q0) * 1024;

    {   // phase 0: load logits tile + q vectors
        const float4* sp = (const float4*)(g_scores + sbase);
        float4* Sd = (float4*)S;
#pragma unroll
        for (int i = 0; i < 8; ++i) Sd[tid + i * 256] = sp[tid + i * 256];
        int ql = tid >> 5, d = tid & 31;
        QS[tid] = g_q[((size_t)(b * 1024 + q0 + ql)) * 512 + h * 32 + d];
    }
    __syncthreads();

    int qA = tid >> 5;      // warp id == q row (uniform per warp)
    int lane = tid & 31;
    float qreg[32];
#pragma unroll
    for (int d = 0; d < 32; ++d) qreg[d] = QS[qA * 32 + d];

    // phase 1: += QK^T
    const float4* kb_all = (const float4*)(g_k + ((size_t)b * 1024) * 512 + h * 32);
    int kl0 = tid >> 3, dq0 = (tid & 7) * 4;
    int kl1 = (tid + 256) >> 3;
    for (int kt = 0; kt < 16; ++kt) {
        const float4* kb = kb_all + (size_t)(kt * 64) * 128;
        float4 t0 = kb[(size_t)kl0 * 128 + (tid & 7)];
        float4 t1 = kb[(size_t)kl1 * 128 + (tid & 7)];
        __syncthreads();
        KV[kl0 * 33 + dq0 + 0] = t0.x; KV[kl0 * 33 + dq0 + 1] = t0.y;
        KV[kl0 * 33 + dq0 + 2] = t0.z; KV[kl0 * 33 + dq0 + 3] = t0.w;
        KV[kl1 * 33 + dq0 + 0] = t1.x; KV[kl1 * 33 + dq0 + 1] = t1.y;
        KV[kl1 * 33 + dq0 + 2] = t1.z; KV[kl1 * 33 + dq0 + 3] = t1.w;
        __syncthreads();
#pragma unroll
        for (int j = 0; j < 2; ++j) {
            int kl = lane + j * 32;
            float acc = 0.f;
#pragma unroll
            for (int d = 0; d < 32; ++d) acc += qreg[d] * KV[kl * 33 + d];
            S[qA * 1024 + kt * 64 + kl] += acc;
        }
    }
    __syncthreads();

    // phase 2: softmax per row (warp w handles row w)
    {
        float* row = S + qA * 1024;
        float mx = -1e30f;
        for (int kk = lane; kk < 1024; kk += 32) mx = fmaxf(mx, row[kk]);
#pragma unroll
        for (int o = 16; o; o >>= 1) mx = fmaxf(mx, __shfl_xor_sync(0xffffffffu, mx, o));
        float sum = 0.f;
        for (int kk = lane; kk < 1024; kk += 32) {
            float e = __expf(row[kk] - mx);
            row[kk] = e;
            sum += e;
        }
#pragma unroll
        for (int o = 16; o; o >>= 1) sum += __shfl_xor_sync(0xffffffffu, sum, o);
        float inv = 1.0f / sum;
        for (int kk = lane; kk < 1024; kk += 32) row[kk] *= inv;
    }
    __syncthreads();

    // phase 3: AV
    const float4* vb_all = (const float4*)(g_v + ((size_t)b * 1024) * 512 + h * 32);
    float acc = 0.f;
    for (int kt = 0; kt < 16; ++kt) {
        const float4* vb = vb_all + (size_t)(kt * 64) * 128;
        float4 t0 = vb[(size_t)kl0 * 128 + (tid & 7)];
        float4 t1 = vb[(size_t)kl1 * 128 + (tid & 7)];
        __syncthreads();
        KV[kl0 * 33 + dq0 + 0] = t0.x; KV[kl0 * 33 + dq0 + 1] = t0.y;
        KV[kl0 * 33 + dq0 + 2] = t0.z; KV[kl0 * 33 + dq0 + 3] = t0.w;
        KV[kl1 * 33 + dq0 + 0] = t1.x; KV[kl1 * 33 + dq0 + 1] = t1.y;
        KV[kl1 * 33 + dq0 + 2] = t1.z; KV[kl1 * 33 + dq0 + 3] = t1.w;
        __syncthreads();
#pragma unroll
        for (int kk = 0; kk < 64; ++kk) {
            float p = S[qA * 1024 + kt * 64 + kk];
            acc += p * KV[kk * 33 + lane];
        }
    }
    size_t oidx = ((size_t)(b * 1024 + q0 + qA)) * 512 + h * 32 + lane;
    g_og[oidx] = acc * g_g[oidx];
}

// ---------------- kernel 4: out = og @ w_o + b_o ----------------
__global__ __launch_bounds__(256) void out_kernel(const float* __restrict__ wo,
                                                  const float* __restrict__ bo,
                                                  float* __restrict__ out) {
    __shared__ float As[16][68];
    __shared__ float Bs[16][68];
    int bx = blockIdx.x;    // 0..7
    int by = blockIdx.y;    // 0..31
    int tid = threadIdx.x;
    int tx = tid & 15, ty = tid >> 4;
    int cl0 = bx * 64;
    float acc[4][4] = {};
    int aRow = tid >> 2, aK4 = (tid & 3) * 4;
    int bK = tid >> 4, bC4 = (tid & 15) * 4;
    for (int k0 = 0; k0 < 512; k0 += 16) {
        float4 va = *(const float4*)(g_og + (size_t)(by * 64 + aRow) * 512 + k0 + aK4);
        float4 vb = *(const float4*)(wo + (size_t)(k0 + bK) * 512 + cl0 + bC4);
        __syncthreads();
        As[aK4 + 0][aRow] = va.x;
        As[aK4 + 1][aRow] = va.y;
        As[aK4 + 2][aRow] = va.z;
        As[aK4 + 3][aRow] = va.w;
        *(float4*)&Bs[bK][bC4] = vb;
        __syncthreads();
#pragma unroll
        for (int kk = 0; kk < 16; ++kk) {
            float4 a = *(const float4*)&As[kk][ty * 4];
            float4 b = *(const float4*)&Bs[kk][tx * 4];
            float ar[4] = {a.x, a.y, a.z, a.w};
            float br[4] = {b.x, b.y, b.z, b.w};
#pragma unroll
            for (int i = 0; i < 4; ++i)
#pragma unroll
                for (int j = 0; j < 4; ++j) acc[i][j] += ar[i] * br[j];
        }
    }
#pragma unroll
    for (int i = 0; i < 4; ++i) {
        int row = by * 64 + ty * 4 + i;
#pragma unroll
        for (int j = 0; j < 4; ++j) {
            int col = cl0 + tx * 4 + j;
            out[(size_t)row * 512 + col] = acc[i][j] + bo[col];
        }
    }
}

// ---------------- launch ----------------
extern "C" void kernel_launch(void* const* d_in, const int* in_sizes, int n_in,
                              void* d_out, int out_size) {
    const float* m     = (const float*)d_in[0];
    const float* z     = (const float*)d_in[1];
    const float* mask  = (const float*)d_in[2];
    const float* ln_m_w = (const float*)d_in[3];
    const float* ln_m_b = (const float*)d_in[4];
    const float* ln_z_w = (const float*)d_in[5];
    const float* ln_z_b = (const float*)d_in[6];
    const float* w_z   = (const float*)d_in[7];
    const float* w_q   = (const float*)d_in[8];
    const float* w_k   = (const float*)d_in[9];
    const float* w_v   = (const float*)d_in[10];
    const float* w_g   = (const float*)d_in[11];
    const float* b_g   = (const float*)d_in[12];
    const float* w_o   = (const float*)d_in[13];
    const float* b_o   = (const float*)d_in[14];
    float* out = (float*)d_out;

    ln_m_kernel<<<BB * NN, 128>>>(m, ln_m_w, ln_m_b);
    proj_kernel<<<dim3(32, 32), 256>>>(w_q, w_k, w_v, w_g, b_g);
    bias_kernel<<<BB * NN, 256>>>(z, mask, ln_z_w, ln_z_b, w_z);
    attn_kernel<<<dim3(128, 32), 256>>>();
    out_kernel<<<dim3(8, 32), 256>>>(w_o, b_o, out);
}

// round 4
// speedup vs baseline: 1.1481x; 1.1481x over previous
#include <cuda_runtime.h>
#include <cuda_fp16.h>
#include <math.h>

#define BB 2
#define NN 1024
#define CIN 512
#define HH 16
#define DH 32
#define CZ 128

// ---------------- scratch (device globals; no allocation) ----------------
__device__ float g_mln[BB * NN * CIN];
__device__ float g_q[BB * NN * CIN];
__device__ float g_kt[BB * CIN * NN];          // k transposed: [b][d][n]
__device__ float g_v[BB * NN * CIN];
__device__ float g_g[BB * NN * CIN];
__device__ float g_og[BB * NN * CIN];
__device__ __half g_probs[(size_t)BB * HH * NN * NN];  // unnormalized exp, fp16 (64MB)
__device__ float g_psum[BB * HH * NN];                  // softmax row sums

__device__ __forceinline__ float comp4(const float4 v, int u) {
    return u == 0 ? v.x : (u == 1 ? v.y : (u == 2 ? v.z : v.w));
}

// ---------------- kernel 1a: LayerNorm(m) ----------------
__global__ __launch_bounds__(128) void ln_m_kernel(const float* __restrict__ m,
                                                   const float* __restrict__ w,
                                                   const float* __restrict__ b) {
    int row = blockIdx.x;
    int tid = threadIdx.x;
    const float4* mp = (const float4*)m + (size_t)row * 128;
    float4 x = mp[tid];
    float s = x.x + x.y + x.z + x.w;
    float q2 = x.x * x.x + x.y * x.y + x.z * x.z + x.w * x.w;
#pragma unroll
    for (int o = 16; o; o >>= 1) {
        s  += __shfl_xor_sync(0xffffffffu, s, o);
        q2 += __shfl_xor_sync(0xffffffffu, q2, o);
    }
    __shared__ float sS[4], sQ[4];
    __shared__ float s_mu, s_rstd;
    int wid = tid >> 5, lane = tid & 31;
    if (lane == 0) { sS[wid] = s; sQ[wid] = q2; }
    __syncthreads();
    if (tid == 0) {
        float ts = sS[0] + sS[1] + sS[2] + sS[3];
        float tq = sQ[0] + sQ[1] + sQ[2] + sQ[3];
        float mu = ts * (1.0f / 512.0f);
        float var = tq * (1.0f / 512.0f) - mu * mu;
        s_mu = mu;
        s_rstd = rsqrtf(var + 1e-5f);
    }
    __syncthreads();
    float mu = s_mu, rstd = s_rstd;
    float4 w4 = ((const float4*)w)[tid];
    float4 b4 = ((const float4*)b)[tid];
    float4 o;
    o.x = (x.x - mu) * rstd * w4.x + b4.x;
    o.y = (x.y - mu) * rstd * w4.y + b4.y;
    o.z = (x.z - mu) * rstd * w4.z + b4.z;
    o.w = (x.w - mu) * rstd * w4.w + b4.w;
    ((float4*)g_mln)[(size_t)row * 128 + tid] = o;
}

// ---------------- kernel 1b: projections q,kT,v,g ----------------
__global__ __launch_bounds__(256) void proj_kernel(const float* __restrict__ wq,
                                                   const float* __restrict__ wk,
                                                   const float* __restrict__ wv,
                                                   const float* __restrict__ wg,
                                                   const float* __restrict__ bg) {
    __shared__ float As[16][68];
    __shared__ float Bs[16][68];
    int bx = blockIdx.x;
    int by = blockIdx.y;
    int tid = threadIdx.x;
    int tx = tid & 15, ty = tid >> 4;
    int sel = bx >> 3;
    int cl0 = (bx & 7) * 64;
    const float* W = (sel == 0) ? wq : (sel == 1) ? wk : (sel == 2) ? wv : wg;
    float acc[4][4] = {};
    int aRow = tid >> 2, aK4 = (tid & 3) * 4;
    int bK = tid >> 4, bC4 = (tid & 15) * 4;
    for (int k0 = 0; k0 < 512; k0 += 16) {
        float4 va = *(const float4*)(g_mln + (size_t)(by * 64 + aRow) * 512 + k0 + aK4);
        float4 vb = *(const float4*)(W + (size_t)(k0 + bK) * 512 + cl0 + bC4);
        __syncthreads();
        As[aK4 + 0][aRow] = va.x;
        As[aK4 + 1][aRow] = va.y;
        As[aK4 + 2][aRow] = va.z;
        As[aK4 + 3][aRow] = va.w;
        *(float4*)&Bs[bK][bC4] = vb;
        __syncthreads();
#pragma unroll
        for (int kk = 0; kk < 16; ++kk) {
            float4 a = *(const float4*)&As[kk][ty * 4];
            float4 b = *(const float4*)&Bs[kk][tx * 4];
            float ar[4] = {a.x, a.y, a.z, a.w};
            float br[4] = {b.x, b.y, b.z, b.w};
#pragma unroll
            for (int i = 0; i < 4; ++i)
#pragma unroll
                for (int j = 0; j < 4; ++j) acc[i][j] += ar[i] * br[j];
        }
    }
    const float qscale = 0.17677669529663687f;
#pragma unroll
    for (int i = 0; i < 4; ++i) {
        int row = by * 64 + ty * 4 + i;
#pragma unroll
        for (int j = 0; j < 4; ++j) {
            int col = cl0 + tx * 4 + j;
            size_t oidx = (size_t)row * 512 + col;
            float v = acc[i][j];
            if (sel == 0)      g_q[oidx] = v * qscale;
            else if (sel == 1) g_kt[((size_t)(row >> 10)) * 512 * 1024 + (size_t)col * 1024 + (row & 1023)] = v;
            else if (sel == 2) g_v[oidx] = v;
            else               g_g[oidx] = 1.0f / (1.0f + __expf(-(v + bg[col])));
        }
    }
}

// ---------------- kernel 2: fused bias + QK + softmax -> fp16 probs ----------------
// smem layout (dynamic): S[16*1024] | wzw[2048] | qs[512] | s1[16] | c0[16]
__global__ __launch_bounds__(256) void bias_attn_kernel(const float* __restrict__ z,
                                                        const float* __restrict__ mask,
                                                        const float* __restrict__ lzw,
                                                        const float* __restrict__ lzb,
                                                        const float* __restrict__ wz) {
    extern __shared__ float smbuf[];
    float* S   = smbuf;                 // 16 rows x 1024
    float* wzw = smbuf + 16384;
    float* qs  = wzw + 2048;
    float* s1  = qs + 512;
    float* c0  = s1 + 16;

    int tid = threadIdx.x;
    int bq = blockIdx.x;
    int b = bq >> 10, q = bq & 1023;

    for (int idx = tid; idx < 2048; idx += 256) {
        int c = idx >> 4;
        wzw[idx] = lzw[c] * wz[idx];
    }
    qs[tid]       = g_q[(size_t)(b * 1024 + q) * 512 + tid];
    qs[tid + 256] = g_q[(size_t)(b * 1024 + q) * 512 + tid + 256];
    __syncthreads();
    if (tid < 16) {
        float a = 0.f, bb2 = 0.f;
        for (int c = 0; c < 128; ++c) {
            a   += wzw[c * 16 + tid];
            bb2 += lzb[c] * wz[c * 16 + tid];
        }
        s1[tid] = a;
        c0[tid] = bb2;
    }
    __syncthreads();

    // ---- phase A: stream z, 16-head projection + LN stats ----
    const float4* zb = (const float4*)z + ((size_t)bq * 1024) * 32;
    const float4* zp0 = zb + (size_t)(tid) * 32;
    const float4* zp1 = zb + (size_t)(tid + 256) * 32;
    const float4* zp2 = zb + (size_t)(tid + 512) * 32;
    const float4* zp3 = zb + (size_t)(tid + 768) * 32;

    float sm[4] = {0, 0, 0, 0}, sq[4] = {0, 0, 0, 0};
    float dot[4][16] = {};

#pragma unroll 2
    for (int c4 = 0; c4 < 32; ++c4) {
        float4 zv0 = zp0[c4];
        float4 zv1 = zp1[c4];
        float4 zv2 = zp2[c4];
        float4 zv3 = zp3[c4];
#pragma unroll
        for (int u = 0; u < 4; ++u) {
            int c = c4 * 4 + u;
            float4 w0 = *(const float4*)&wzw[c * 16 + 0];
            float4 w1 = *(const float4*)&wzw[c * 16 + 4];
            float4 w2 = *(const float4*)&wzw[c * 16 + 8];
            float4 w3 = *(const float4*)&wzw[c * 16 + 12];
            float xs[4] = {comp4(zv0, u), comp4(zv1, u), comp4(zv2, u), comp4(zv3, u)};
#pragma unroll
            for (int j = 0; j < 4; ++j) {
                float x = xs[j];
                sm[j] += x;
                sq[j] += x * x;
                dot[j][0]  += x * w0.x;  dot[j][1]  += x * w0.y;
                dot[j][2]  += x * w0.z;  dot[j][3]  += x * w0.w;
                dot[j][4]  += x * w1.x;  dot[j][5]  += x * w1.y;
                dot[j][6]  += x * w1.z;  dot[j][7]  += x * w1.w;
                dot[j][8]  += x * w2.x;  dot[j][9]  += x * w2.y;
                dot[j][10] += x * w2.z;  dot[j][11] += x * w2.w;
                dot[j][12] += x * w3.x;  dot[j][13] += x * w3.y;
                dot[j][14] += x * w3.z;  dot[j][15] += x * w3.w;
            }
        }
    }

#pragma unroll
    for (int j = 0; j < 4; ++j) {
        int k = tid + 256 * j;
        float mu = sm[j] * (1.0f / 128.0f);
        float var = sq[j] * (1.0f / 128.0f) - mu * mu;
        float rstd = rsqrtf(var + 1e-5f);
        float mb = 1e9f * (mask[b * 1024 + k] - 1.0f);
#pragma unroll
        for (int h = 0; h < 16; ++h)
            S[h * 1024 + k] = rstd * (dot[j][h] - mu * s1[h]) + c0[h] + mb;
    }
    __syncthreads();

    // ---- phase B: S[h][k] += q . k   (warp w owns heads 2w, 2w+1) ----
    int wid = tid >> 5, lane = tid & 31;
    const float* kt = g_kt + (size_t)b * 512 * 1024;
#pragma unroll
    for (int hh = 0; hh < 2; ++hh) {
        int h = wid * 2 + hh;
        for (int kc = 0; kc < 8; ++kc) {
            int k0 = kc * 128 + lane * 4;
            float ax = 0.f, ay = 0.f, az = 0.f, aw = 0.f;
#pragma unroll
            for (int d = 0; d < 32; ++d) {
                float qd = qs[h * 32 + d];
                float4 kv = *(const float4*)(kt + (size_t)(h * 32 + d) * 1024 + k0);
                ax += qd * kv.x; ay += qd * kv.y;
                az += qd * kv.z; aw += qd * kv.w;
            }
            float4 s = *(float4*)&S[h * 1024 + k0];
            s.x += ax; s.y += ay; s.z += az; s.w += aw;
            *(float4*)&S[h * 1024 + k0] = s;
        }
    }

    // ---- phase C: softmax per row (warp-private rows, no barrier needed) ----
#pragma unroll
    for (int hh = 0; hh < 2; ++hh) {
        int h = wid * 2 + hh;
        float* row = &S[h * 1024];
        float mx = -1e30f;
#pragma unroll
        for (int i = 0; i < 8; ++i) {
            float4 v = *(const float4*)&row[lane * 4 + i * 128];
            mx = fmaxf(mx, fmaxf(fmaxf(v.x, v.y), fmaxf(v.z, v.w)));
        }
#pragma unroll
        for (int o = 16; o; o >>= 1) mx = fmaxf(mx, __shfl_xor_sync(0xffffffffu, mx, o));

        __half* prow = g_probs + (((size_t)(b * 16 + h)) * 1024 + q) * 1024;
        float sum = 0.f;
#pragma unroll
        for (int i = 0; i < 16; ++i) {
            int kk = (lane + i * 32) * 2;
            float2 v = *(const float2*)&row[kk];
            float e0 = __expf(v.x - mx);
            float e1 = __expf(v.y - mx);
            sum += e0 + e1;
            *(__half2*)(prow + kk) = __floats2half2_rn(e0, e1);
        }
#pragma unroll
        for (int o = 16; o; o >>= 1) sum += __shfl_xor_sync(0xffffffffu, sum, o);
        if (lane == 0) g_psum[(b * 16 + h) * 1024 + q] = sum;
    }
}

// ---------------- kernel 3: AV + gate ----------------
__global__ __launch_bounds__(256) void av_kernel() {
    __shared__ __half Ps[128][72];     // 128 q x 64 k (+pad)
    __shared__ float  Vs[64][36];      // 64 k x 32 d (+pad)
    int tid = threadIdx.x;
    int tx = tid & 7;                  // d group (tx*4)
    int ty = tid >> 3;                 // q group (ty*4)
    int bh = blockIdx.y;
    int b = bh >> 4, h = bh & 15;
    int q0 = blockIdx.x * 128;

    const __half* pb = g_probs + ((size_t)bh * 1024 + q0) * 1024;
    const float* vb = g_v + (size_t)b * 1024 * 512 + h * 32;

    float acc[4][4] = {};

    for (int kt = 0; kt < 16; ++kt) {
        __syncthreads();
#pragma unroll
        for (int u = 0; u < 4; ++u) {
            int id = tid + 256 * u;
            int row = id >> 3, c8 = id & 7;
            *(uint4*)&Ps[row][c8 * 8] = *(const uint4*)(pb + (size_t)row * 1024 + kt * 64 + c8 * 8);
        }
#pragma unroll
        for (int u = 0; u < 2; ++u) {
            int id = tid + 256 * u;
            int row = id >> 3, d4 = id & 7;
            *(float4*)&Vs[row][d4 * 4] = *(const float4*)(vb + (size_t)(kt * 64 + row) * 512 + d4 * 4);
        }
        __syncthreads();
#pragma unroll 4
        for (int k2 = 0; k2 < 32; ++k2) {
            int kk = k2 * 2;
            float4 v0 = *(const float4*)&Vs[kk][tx * 4];
            float4 v1 = *(const float4*)&Vs[kk + 1][tx * 4];
#pragma unroll
            for (int i = 0; i < 4; ++i) {
                float2 pf = __half22float2(*(const __half2*)&Ps[ty * 4 + i][kk]);
                acc[i][0] += pf.x * v0.x + pf.y * v1.x;
                acc[i][1] += pf.x * v0.y + pf.y * v1.y;
                acc[i][2] += pf.x * v0.z + pf.y * v1.z;
                acc[i][3] += pf.x * v0.w + pf.y * v1.w;
            }
        }
    }

#pragma unroll
    for (int i = 0; i < 4; ++i) {
        int q = q0 + ty * 4 + i;
        float inv = 1.0f / g_psum[bh * 1024 + q];
        size_t gi = ((size_t)(b * 1024 + q)) * 512 + h * 32 + tx * 4;
        float4 gv = *(const float4*)&g_g[gi];
        float4 o;
        o.x = acc[i][0] * inv * gv.x;
        o.y = acc[i][1] * inv * gv.y;
        o.z = acc[i][2] * inv * gv.z;
        o.w = acc[i][3] * inv * gv.w;
        *(float4*)&g_og[gi] = o;
    }
}

// ---------------- kernel 4: out = og @ w_o + b_o ----------------
__global__ __launch_bounds__(256) void out_kernel(const float* __restrict__ wo,
                                                  const float* __restrict__ bo,
                                                  float* __restrict__ out) {
    __shared__ float As[16][68];
    __shared__ float Bs[16][68];
    int bx = blockIdx.x;
    int by = blockIdx.y;
    int tid = threadIdx.x;
    int tx = tid & 15, ty = tid >> 4;
    int cl0 = bx * 64;
    float acc[4][4] = {};
    int aRow = tid >> 2, aK4 = (tid & 3) * 4;
    int bK = tid >> 4, bC4 = (tid & 15) * 4;
    for (int k0 = 0; k0 < 512; k0 += 16) {
        float4 va = *(const float4*)(g_og + (size_t)(by * 64 + aRow) * 512 + k0 + aK4);
        float4 vb = *(const float4*)(wo + (size_t)(k0 + bK) * 512 + cl0 + bC4);
        __syncthreads();
        As[aK4 + 0][aRow] = va.x;
        As[aK4 + 1][aRow] = va.y;
        As[aK4 + 2][aRow] = va.z;
        As[aK4 + 3][aRow] = va.w;
        *(float4*)&Bs[bK][bC4] = vb;
        __syncthreads();
#pragma unroll
        for (int kk = 0; kk < 16; ++kk) {
            float4 a = *(const float4*)&As[kk][ty * 4];
            float4 b = *(const float4*)&Bs[kk][tx * 4];
            float ar[4] = {a.x, a.y, a.z, a.w};
            float br[4] = {b.x, b.y, b.z, b.w};
#pragma unroll
            for (int i = 0; i < 4; ++i)
#pragma unroll
                for (int j = 0; j < 4; ++j) acc[i][j] += ar[i] * br[j];
        }
    }
#pragma unroll
    for (int i = 0; i < 4; ++i) {
        int row = by * 64 + ty * 4 + i;
#pragma unroll
        for (int j = 0; j < 4; ++j) {
            int col = cl0 + tx * 4 + j;
            out[(size_t)row * 512 + col] = acc[i][j] + bo[col];
        }
    }
}

// ---------------- launch ----------------
extern "C" void kernel_launch(void* const* d_in, const int* in_sizes, int n_in,
                              void* d_out, int out_size) {
    const float* m      = (const float*)d_in[0];
    const float* z      = (const float*)d_in[1];
    const float* mask   = (const float*)d_in[2];
    const float* ln_m_w = (const float*)d_in[3];
    const float* ln_m_b = (const float*)d_in[4];
    const float* ln_z_w = (const float*)d_in[5];
    const float* ln_z_b = (const float*)d_in[6];
    const float* w_z    = (const float*)d_in[7];
    const float* w_q    = (const float*)d_in[8];
    const float* w_k    = (const float*)d_in[9];
    const float* w_v    = (const float*)d_in[10];
    const float* w_g    = (const float*)d_in[11];
    const float* b_g    = (const float*)d_in[12];
    const float* w_o    = (const float*)d_in[13];
    const float* b_o    = (const float*)d_in[14];
    float* out = (float*)d_out;

    const int smem_bias = (16384 + 2048 + 512 + 32) * 4;   // 75904 B
    cudaFuncSetAttribute(bias_attn_kernel,
                         cudaFuncAttributeMaxDynamicSharedMemorySize, smem_bias);

    ln_m_kernel<<<BB * NN, 128>>>(m, ln_m_w, ln_m_b);
    proj_kernel<<<dim3(32, 32), 256>>>(w_q, w_k, w_v, w_g, b_g);
    bias_attn_kernel<<<BB * NN, 256, smem_bias>>>(z, mask, ln_z_w, ln_z_b, w_z);
    av_kernel<<<dim3(8, 32), 256>>>();
    out_kernel<<<dim3(8, 32), 256>>>(w_o, b_o, out);
}

// round 6
// speedup vs baseline: 1.3178x; 1.1478x over previous
#include <cuda_runtime.h>
#include <cuda_fp16.h>
#include <math.h>

#define BB 2
#define NN 1024
#define CIN 512
#define HH 16
#define DH 32
#define CZ 128

// ---------------- scratch (device globals; no allocation) ----------------
__device__ float g_mln[BB * NN * CIN];
__device__ float g_q[BB * NN * CIN];
__device__ float g_k[BB * NN * CIN];
__device__ float g_v[BB * NN * CIN];
__device__ float g_g[BB * NN * CIN];
__device__ float g_og[BB * NN * CIN];
__device__ float g_qk[(size_t)BB * HH * NN * NN];       // QK^T logits fp32 (128MB)
__device__ __half g_probs[(size_t)BB * HH * NN * NN];   // unnormalized exp fp16 (64MB)
__device__ float g_psum[BB * HH * NN];                  // softmax row sums

__device__ __forceinline__ float comp4(const float4 v, int u) {
    return u == 0 ? v.x : (u == 1 ? v.y : (u == 2 ? v.z : v.w));
}

// ---------------- kernel 1a: LayerNorm(m) ----------------
__global__ __launch_bounds__(128) void ln_m_kernel(const float* __restrict__ m,
                                                   const float* __restrict__ w,
                                                   const float* __restrict__ b) {
    int row = blockIdx.x;
    int tid = threadIdx.x;
    const float4* mp = (const float4*)m + (size_t)row * 128;
    float4 x = mp[tid];
    float s = x.x + x.y + x.z + x.w;
    float q2 = x.x * x.x + x.y * x.y + x.z * x.z + x.w * x.w;
#pragma unroll
    for (int o = 16; o; o >>= 1) {
        s  += __shfl_xor_sync(0xffffffffu, s, o);
        q2 += __shfl_xor_sync(0xffffffffu, q2, o);
    }
    __shared__ float sS[4], sQ[4];
    __shared__ float s_mu, s_rstd;
    int wid = tid >> 5, lane = tid & 31;
    if (lane == 0) { sS[wid] = s; sQ[wid] = q2; }
    __syncthreads();
    if (tid == 0) {
        float ts = sS[0] + sS[1] + sS[2] + sS[3];
        float tq = sQ[0] + sQ[1] + sQ[2] + sQ[3];
        float mu = ts * (1.0f / 512.0f);
        float var = tq * (1.0f / 512.0f) - mu * mu;
        s_mu = mu;
        s_rstd = rsqrtf(var + 1e-5f);
    }
    __syncthreads();
    float mu = s_mu, rstd = s_rstd;
    float4 w4 = ((const float4*)w)[tid];
    float4 b4 = ((const float4*)b)[tid];
    float4 o;
    o.x = (x.x - mu) * rstd * w4.x + b4.x;
    o.y = (x.y - mu) * rstd * w4.y + b4.y;
    o.z = (x.z - mu) * rstd * w4.z + b4.z;
    o.w = (x.w - mu) * rstd * w4.w + b4.w;
    ((float4*)g_mln)[(size_t)row * 128 + tid] = o;
}

// ---------------- kernel 1b: projections q,k,v,g ----------------
__global__ __launch_bounds__(256) void proj_kernel(const float* __restrict__ wq,
                                                   const float* __restrict__ wk,
                                                   const float* __restrict__ wv,
                                                   const float* __restrict__ wg,
                                                   const float* __restrict__ bg) {
    __shared__ float As[16][68];
    __shared__ float Bs[16][68];
    int bx = blockIdx.x;
    int by = blockIdx.y;
    int tid = threadIdx.x;
    int tx = tid & 15, ty = tid >> 4;
    int sel = bx >> 3;
    int cl0 = (bx & 7) * 64;
    const float* W = (sel == 0) ? wq : (sel == 1) ? wk : (sel == 2) ? wv : wg;
    float acc[4][4] = {};
    int aRow = tid >> 2, aK4 = (tid & 3) * 4;
    int bK = tid >> 4, bC4 = (tid & 15) * 4;
    for (int k0 = 0; k0 < 512; k0 += 16) {
        float4 va = *(const float4*)(g_mln + (size_t)(by * 64 + aRow) * 512 + k0 + aK4);
        float4 vb = *(const float4*)(W + (size_t)(k0 + bK) * 512 + cl0 + bC4);
        __syncthreads();
        As[aK4 + 0][aRow] = va.x;
        As[aK4 + 1][aRow] = va.y;
        As[aK4 + 2][aRow] = va.z;
        As[aK4 + 3][aRow] = va.w;
        *(float4*)&Bs[bK][bC4] = vb;
        __syncthreads();
#pragma unroll
        for (int kk = 0; kk < 16; ++kk) {
            float4 a = *(const float4*)&As[kk][ty * 4];
            float4 b = *(const float4*)&Bs[kk][tx * 4];
            float ar[4] = {a.x, a.y, a.z, a.w};
            float br[4] = {b.x, b.y, b.z, b.w};
#pragma unroll
            for (int i = 0; i < 4; ++i)
#pragma unroll
                for (int j = 0; j < 4; ++j) acc[i][j] += ar[i] * br[j];
        }
    }
    const float qscale = 0.17677669529663687f;
#pragma unroll
    for (int i = 0; i < 4; ++i) {
        int row = by * 64 + ty * 4 + i;
#pragma unroll
        for (int j = 0; j < 4; ++j) {
            int col = cl0 + tx * 4 + j;
            size_t oidx = (size_t)row * 512 + col;
            float v = acc[i][j];
            if (sel == 0)      g_q[oidx] = v * qscale;
            else if (sel == 1) g_k[oidx] = v;
            else if (sel == 2) g_v[oidx] = v;
            else               g_g[oidx] = 1.0f / (1.0f + __expf(-(v + bg[col])));
        }
    }
}

// ---------------- kernel 1c: qk[b,h,q,k] = q . k  (batched GEMM) ----------------
__global__ __launch_bounds__(512) void qk_kernel() {
    __shared__ float Qs[128][36];
    __shared__ float Ks[128][36];
    int tid = threadIdx.x;
    int bh = blockIdx.y;
    int b = bh >> 4, h = bh & 15;
    int q0 = (blockIdx.x >> 3) * 128;
    int k0 = (blockIdx.x & 7) * 128;
    const float* qb = g_q + (size_t)(b * 1024) * 512 + h * 32;
    const float* kb = g_k + (size_t)(b * 1024) * 512 + h * 32;
#pragma unroll
    for (int u = 0; u < 2; ++u) {
        int fid = tid + 512 * u;
        int row = fid >> 3, d4 = (fid & 7) * 4;
        *(float4*)&Qs[row][d4] = *(const float4*)(qb + (size_t)(q0 + row) * 512 + d4);
        *(float4*)&Ks[row][d4] = *(const float4*)(kb + (size_t)(k0 + row) * 512 + d4);
    }
    __syncthreads();
    int tx = tid & 15, ty = tid >> 4;          // ty 0..31: q rows ty+32i; tx: k cols tx+16j
    float acc[4][8] = {};
#pragma unroll
    for (int d4 = 0; d4 < 8; ++d4) {
        float4 av[4], bv[8];
#pragma unroll
        for (int i = 0; i < 4; ++i) av[i] = *(const float4*)&Qs[ty + 32 * i][d4 * 4];
#pragma unroll
        for (int j = 0; j < 8; ++j) bv[j] = *(const float4*)&Ks[tx + 16 * j][d4 * 4];
#pragma unroll
        for (int i = 0; i < 4; ++i)
#pragma unroll
            for (int j = 0; j < 8; ++j)
                acc[i][j] += av[i].x * bv[j].x + av[i].y * bv[j].y +
                             av[i].z * bv[j].z + av[i].w * bv[j].w;
    }
    float* ob = g_qk + ((size_t)bh * 1024 + q0) * 1024 + k0;
#pragma unroll
    for (int i = 0; i < 4; ++i)
#pragma unroll
        for (int j = 0; j < 8; ++j)
            ob[(size_t)(ty + 32 * i) * 1024 + tx + 16 * j] = acc[i][j];
}

// ---------------- kernel 2: fused pair-bias + (+qk) + softmax -> fp16 probs ----------------
// dyn smem: S[16*1024] | wzw_h2[128*8 half2] | s1[16] | c0[16]
__global__ __launch_bounds__(512) void bias_attn_kernel(const float* __restrict__ z,
                                                        const float* __restrict__ mask,
                                                        const float* __restrict__ lzw,
                                                        const float* __restrict__ lzb,
                                                        const float* __restrict__ wz) {
    extern __shared__ float smbuf[];
    float* S = smbuf;                                     // 16 x 1024
    __half2* wzw_h2 = (__half2*)(smbuf + 16384);          // [c][p] head-pair weights
    float* s1 = smbuf + 16384 + 1024;
    float* c0 = s1 + 16;

    int tid = threadIdx.x;
    int bq = blockIdx.x;
    int b = bq >> 10, q = bq & 1023;

    // weights: wzw[c][h] = lzw[c]*wz[c][h], packed per head-pair
    for (int idx = tid; idx < 1024; idx += 512) {
        int c = idx >> 3, p = idx & 7;
        float lw = lzw[c];
        wzw_h2[idx] = __floats2half2_rn(lw * wz[c * 16 + 2 * p],
                                        lw * wz[c * 16 + 2 * p + 1]);
    }
    if (tid < 16) {
        float a = 0.f, bb2 = 0.f;
#pragma unroll 4
        for (int c = 0; c < 128; ++c) {
            a   += lzw[c] * wz[c * 16 + tid];
            bb2 += lzb[c] * wz[c * 16 + tid];
        }
        s1[tid] = a;
        c0[tid] = bb2;
    }
    __syncthreads();

    // ---- phase A: stream z; per-thread 2 k-streams; HFMA2 head-pair dots ----
    const float4* zb = (const float4*)z + ((size_t)bq * 1024) * 32;
    const float4* zp0 = zb + (size_t)tid * 32;
    const float4* zp1 = zb + (size_t)(tid + 512) * 32;

    float sm0 = 0.f, sq0 = 0.f, sm1 = 0.f, sq1 = 0.f;
    float d0[16] = {}, d1[16] = {};
    __half2 h0[8], h1[8];
    const __half2 hz = __float2half2_rn(0.f);
#pragma unroll
    for (int p = 0; p < 8; ++p) { h0[p] = hz; h1[p] = hz; }

#pragma unroll 1
    for (int g = 0; g < 4; ++g) {
#pragma unroll
        for (int c8 = 0; c8 < 8; ++c8) {
            int c4 = g * 8 + c8;
            float4 zv0 = zp0[c4];
            float4 zv1 = zp1[c4];
#pragma unroll
            for (int u = 0; u < 4; ++u) {
                int c = c4 * 4 + u;
                float x0 = comp4(zv0, u);
                float x1 = comp4(zv1, u);
                sm0 += x0; sq0 += x0 * x0;
                sm1 += x1; sq1 += x1 * x1;
                __half2 xh0 = __float2half2_rn(x0);
                __half2 xh1 = __float2half2_rn(x1);
                const __half2* wr = wzw_h2 + c * 8;
#pragma unroll
                for (int p = 0; p < 8; ++p) {
                    __half2 w = wr[p];
                    h0[p] = __hfma2(xh0, w, h0[p]);
                    h1[p] = __hfma2(xh1, w, h1[p]);
                }
            }
        }
        // flush fp16 accumulators -> fp32
#pragma unroll
        for (int p = 0; p < 8; ++p) {
            float2 f0 = __half22float2(h0[p]);
            float2 f1 = __half22float2(h1[p]);
            d0[2 * p]     += f0.x;
            d0[2 * p + 1] += f0.y;
            d1[2 * p]     += f1.x;
            d1[2 * p + 1] += f1.y;
            h0[p] = hz;
            h1[p] = hz;
        }
    }

    {   // epilogue: LN combine, write bias rows to smem
        int k0 = tid, k1 = tid + 512;
        float mu0 = sm0 * (1.0f / 128.0f);
        float rstd0 = rsqrtf(sq0 * (1.0f / 128.0f) - mu0 * mu0 + 1e-5f);
        float mb0 = 1e9f * (mask[b * 1024 + k0] - 1.0f);
        float mu1 = sm1 * (1.0f / 128.0f);
        float rstd1 = rsqrtf(sq1 * (1.0f / 128.0f) - mu1 * mu1 + 1e-5f);
        float mb1 = 1e9f * (mask[b * 1024 + k1] - 1.0f);
#pragma unroll
        for (int h = 0; h < 16; ++h) {
            S[h * 1024 + k0] = rstd0 * (d0[h] - mu0 * s1[h]) + c0[h] + mb0;
            S[h * 1024 + k1] = rstd1 * (d1[h] - mu1 * s1[h]) + c0[h] + mb1;
        }
    }
    __syncthreads();

    // ---- phase B: warp w owns head w: add qk logits, softmax, fp16 probs ----
    {
        int h = tid >> 5, lane = tid & 31;
        const float4* qkr = (const float4*)(g_qk + (((size_t)(b * 16 + h)) * 1024 + q) * 1024);
        float4 sv[8];
        float mx = -1e30f;
#pragma unroll
        for (int i = 0; i < 8; ++i) {
            float4 s = *(const float4*)&S[h * 1024 + lane * 4 + i * 128];
            float4 qk = qkr[lane + i * 32];
            s.x += qk.x; s.y += qk.y; s.z += qk.z; s.w += qk.w;
            sv[i] = s;
            mx = fmaxf(mx, fmaxf(fmaxf(s.x, s.y), fmaxf(s.z, s.w)));
        }
#pragma unroll
        for (int o = 16; o; o >>= 1) mx = fmaxf(mx, __shfl_xor_sync(0xffffffffu, mx, o));

        __half* prow = g_probs + (((size_t)(b * 16 + h)) * 1024 + q) * 1024;
        float sum = 0.f;
#pragma unroll
        for (int i = 0; i < 8; ++i) {
            float e0 = __expf(sv[i].x - mx);
            float e1 = __expf(sv[i].y - mx);
            float e2 = __expf(sv[i].z - mx);
            float e3 = __expf(sv[i].w - mx);
            sum += (e0 + e1) + (e2 + e3);
            __half2 p0 = __floats2half2_rn(e0, e1);
            __half2 p1 = __floats2half2_rn(e2, e3);
            uint2 pk;
            pk.x = reinterpret_cast<unsigned int&>(p0);
            pk.y = reinterpret_cast<unsigned int&>(p1);
            *(uint2*)(prow + lane * 4 + i * 128) = pk;
        }
#pragma unroll
        for (int o = 16; o; o >>= 1) sum += __shfl_xor_sync(0xffffffffu, sum, o);
        if (lane == 0) g_psum[(b * 16 + h) * 1024 + q] = sum;
    }
}

// ---------------- kernel 3: AV + gate ----------------
__global__ __launch_bounds__(256) void av_kernel() {
    __shared__ __half Ps[128][72];
    __shared__ float  Vs[64][36];
    int tid = threadIdx.x;
    int tx = tid & 7;
    int ty = tid >> 3;
    int bh = blockIdx.y;
    int b = bh >> 4, h = bh & 15;
    int q0 = blockIdx.x * 128;

    const __half* pb = g_probs + ((size_t)bh * 1024 + q0) * 1024;
    const float* vb = g_v + (size_t)b * 1024 * 512 + h * 32;

    float acc[4][4] = {};

    for (int kt = 0; kt < 16; ++kt) {
        __syncthreads();
#pragma unroll
        for (int u = 0; u < 4; ++u) {
            int id = tid + 256 * u;
            int row = id >> 3, c8 = id & 7;
            *(uint4*)&Ps[row][c8 * 8] = *(const uint4*)(pb + (size_t)row * 1024 + kt * 64 + c8 * 8);
        }
#pragma unroll
        for (int u = 0; u < 2; ++u) {
            int id = tid + 256 * u;
            int row = id >> 3, d4 = id & 7;
            *(float4*)&Vs[row][d4 * 4] = *(const float4*)(vb + (size_t)(kt * 64 + row) * 512 + d4 * 4);
        }
        __syncthreads();
#pragma unroll 4
        for (int k2 = 0; k2 < 32; ++k2) {
            int kk = k2 * 2;
            float4 v0 = *(const float4*)&Vs[kk][tx * 4];
            float4 v1 = *(const float4*)&Vs[kk + 1][tx * 4];
#pragma unroll
            for (int i = 0; i < 4; ++i) {
                float2 pf = __half22float2(*(const __half2*)&Ps[ty * 4 + i][kk]);
                acc[i][0] += pf.x * v0.x + pf.y * v1.x;
                acc[i][1] += pf.x * v0.y + pf.y * v1.y;
                acc[i][2] += pf.x * v0.z + pf.y * v1.z;
                acc[i][3] += pf.x * v0.w + pf.y * v1.w;
            }
        }
    }

#pragma unroll
    for (int i = 0; i < 4; ++i) {
        int q = q0 + ty * 4 + i;
        float inv = 1.0f / g_psum[bh * 1024 + q];
        size_t gi = ((size_t)(b * 1024 + q)) * 512 + h * 32 + tx * 4;
        float4 gv = *(const float4*)&g_g[gi];
        float4 o;
        o.x = acc[i][0] * inv * gv.x;
        o.y = acc[i][1] * inv * gv.y;
        o.z = acc[i][2] * inv * gv.z;
        o.w = acc[i][3] * inv * gv.w;
        *(float4*)&g_og[gi] = o;
    }
}

// ---------------- kernel 4: out = og @ w_o + b_o ----------------
__global__ __launch_bounds__(256) void out_kernel(const float* __restrict__ wo,
                                                  const float* __restrict__ bo,
                                                  float* __restrict__ out) {
    __shared__ float As[16][68];
    __shared__ float Bs[16][68];
    int bx = blockIdx.x;
    int by = blockIdx.y;
    int tid = threadIdx.x;
    int tx = tid & 15, ty = tid >> 4;
    int cl0 = bx * 64;
    float acc[4][4] = {};
    int aRow = tid >> 2, aK4 = (tid & 3) * 4;
    int bK = tid >> 4, bC4 = (tid & 15) * 4;
    for (int k0 = 0; k0 < 512; k0 += 16) {
        float4 va = *(const float4*)(g_og + (size_t)(by * 64 + aRow) * 512 + k0 + aK4);
        float4 vb = *(const float4*)(wo + (size_t)(k0 + bK) * 512 + cl0 + bC4);
        __syncthreads();
        As[aK4 + 0][aRow] = va.x;
        As[aK4 + 1][aRow] = va.y;
        As[aK4 + 2][aRow] = va.z;
        As[aK4 + 3][aRow] = va.w;
        *(float4*)&Bs[bK][bC4] = vb;
        __syncthreads();
#pragma unroll
        for (int kk = 0; kk < 16; ++kk) {
            float4 a = *(const float4*)&As[kk][ty * 4];
            float4 b = *(const float4*)&Bs[kk][tx * 4];
            float ar[4] = {a.x, a.y, a.z, a.w};
            float br[4] = {b.x, b.y, b.z, b.w};
#pragma unroll
            for (int i = 0; i < 4; ++i)
#pragma unroll
                for (int j = 0; j < 4; ++j) acc[i][j] += ar[i] * br[j];
        }
    }
#pragma unroll
    for (int i = 0; i < 4; ++i) {
        int row = by * 64 + ty * 4 + i;
#pragma unroll
        for (int j = 0; j < 4; ++j) {
            int col = cl0 + tx * 4 + j;
            out[(size_t)row * 512 + col] = acc[i][j] + bo[col];
        }
    }
}

// ---------------- launch ----------------
extern "C" void kernel_launch(void* const* d_in, const int* in_sizes, int n_in,
                              void* d_out, int out_size) {
    const float* m      = (const float*)d_in[0];
    const float* z      = (const float*)d_in[1];
    const float* mask   = (const float*)d_in[2];
    const float* ln_m_w = (const float*)d_in[3];
    const float* ln_m_b = (const float*)d_in[4];
    const float* ln_z_w = (const float*)d_in[5];
    const float* ln_z_b = (const float*)d_in[6];
    const float* w_z    = (const float*)d_in[7];
    const float* w_q    = (const float*)d_in[8];
    const float* w_k    = (const float*)d_in[9];
    const float* w_v    = (const float*)d_in[10];
    const float* w_g    = (const float*)d_in[11];
    const float* b_g    = (const float*)d_in[12];
    const float* w_o    = (const float*)d_in[13];
    const float* b_o    = (const float*)d_in[14];
    float* out = (float*)d_out;

    const int smem_bias = (16384 + 1024 + 32) * 4;   // 69760 B
    cudaFuncSetAttribute(bias_attn_kernel,
                         cudaFuncAttributeMaxDynamicSharedMemorySize, smem_bias);

    ln_m_kernel<<<BB * NN, 128>>>(m, ln_m_w, ln_m_b);
    proj_kernel<<<dim3(32, 32), 256>>>(w_q, w_k, w_v, w_g, b_g);
    qk_kernel<<<dim3(64, 32), 512>>>();
    bias_attn_kernel<<<BB * NN, 512, smem_bias>>>(z, mask, ln_z_w, ln_z_b, w_z);
    av_kernel<<<dim3(8, 32), 256>>>();
    out_kernel<<<dim3(8, 32), 256>>>(w_o, b_o, out);
}